// round 8
// baseline (speedup 1.0000x reference)
#include <cuda_runtime.h>
#include <cuda_bf16.h>
#include <cstdint>

#define NUM_EMB 32
#define ADIM 32
#define HID 1024
#define BB 128
#define TT 64
#define ROWS_TOTAL (BB*TT)   /* 8192 grouped rows */

// ---------------- scratch (device globals; no allocs allowed) ----------------
__device__ float g_aemb[(ROWS_TOTAL + 128) * HID];   // grouped a_emb (tf32-rounded), +pad rows
__device__ float g_h   [(ROWS_TOTAL + 128) * HID];   // grouped hidden (tf32-rounded), +pad rows
__device__ float g_tau [BB * HID];                   // grouped tau
__device__ float g_t2  [BB * HID];                   // grouped tau@W2b + b2
__device__ int   g_batch_of_pos[BB];
__device__ int   g_seg_start[NUM_EMB + 1];
__device__ int   g_mb_cat[128], g_mb_row[128], g_mb_rows[128];
__device__ int   g_mb_count;

// ---------------- helpers ----------------
__device__ __forceinline__ unsigned tf32r_bits(float x) {
    unsigned r;
    asm("cvt.rna.tf32.f32 %0, %1;" : "=r"(r) : "f"(x));
    return r;
}
__device__ __forceinline__ float tf32r(float x) {
    return __uint_as_float(tf32r_bits(x));
}
__device__ __forceinline__ void cpasync16(void* dst, const void* src) {
    unsigned s = (unsigned)__cvta_generic_to_shared(dst);
    asm volatile("cp.async.cg.shared.global [%0], [%1], 16;" :: "r"(s), "l"(src));
}
__device__ __forceinline__ void mma_tf32(float c[4], const unsigned a[4], const unsigned b[2]) {
    asm volatile(
        "mma.sync.aligned.m16n8k8.row.col.f32.tf32.tf32.f32 "
        "{%0,%1,%2,%3}, {%4,%5,%6,%7}, {%8,%9}, {%0,%1,%2,%3};"
        : "+f"(c[0]), "+f"(c[1]), "+f"(c[2]), "+f"(c[3])
        : "r"(a[0]), "r"(a[1]), "r"(a[2]), "r"(a[3]), "r"(b[0]), "r"(b[1]));
}

// ---------------- kernel 0: category grouping + mblock table (parallel) ----------------
__global__ void setup_kernel(const int* __restrict__ cats) {
    __shared__ int cnt[NUM_EMB], segs[NUM_EMB + 1], cur[NUM_EMB];
    int t = threadIdx.x;                 // 128 threads
    if (t < NUM_EMB) cnt[t] = 0;
    __syncthreads();
    int c = cats[t];                     // t in [0, BB)
    atomicAdd(&cnt[c], 1);
    __syncthreads();
    if (t == 0) {
        int s = 0;
        for (int i = 0; i < NUM_EMB; i++) { segs[i] = s; cur[i] = s; s += cnt[i]; }
        segs[NUM_EMB] = s;
    }
    __syncthreads();
    if (t <= NUM_EMB) g_seg_start[t] = segs[t];
    int p = atomicAdd(&cur[c], 1);       // order within a category is irrelevant
    g_batch_of_pos[p] = t;
    __syncthreads();
    if (t == 0) {
        int nmb = 0;
        for (int i = 0; i < NUM_EMB; i++) {
            int rows = cnt[i] * TT;
            int r0 = segs[i] * TT;
            for (int r = 0; r < rows; r += 128) {
                g_mb_cat[nmb] = i;
                g_mb_row[nmb] = r0 + r;
                g_mb_rows[nmb] = (rows - r < 128) ? (rows - r) : 128;
                nmb++;
            }
        }
        g_mb_count = nmb;
    }
}

// ---------------- kernel 1: tau (fp64 trig, grouped layout) ----------------
__global__ void tau_kernel(const float* __restrict__ ts) {
    int pos = blockIdx.x;
    int j = threadIdx.x;               // 0..511
    int b = g_batch_of_pos[pos];
    double t = (double)ts[b];
    double f = exp(-9.210340371976184 * ((double)j) / 512.0);
    double ph = t * f;
    g_tau[pos * HID + j]       = (float)sin(ph);
    g_tau[pos * HID + 512 + j] = (float)cos(ph);
}

// ---------------- kernel 2: a_emb = actions @ W1 + b1 (grouped, tf32-rounded) ----------------
__global__ void aemb_kernel(const float* __restrict__ actions,
                            const float* __restrict__ W1w,
                            const float* __restrict__ W1b,
                            const int*   __restrict__ cats) {
    __shared__ float As[TT * ADIM];
    int pos = blockIdx.x;
    int tid = threadIdx.x;             // 256 threads
    int b = g_batch_of_pos[pos];
    int c = cats[b];
    for (int i = tid; i < TT * ADIM; i += 256)
        As[i] = actions[b * TT * ADIM + i];
    __syncthreads();
    const float* W = W1w + (size_t)c * ADIM * HID;
    const float* bias = W1b + (size_t)c * HID;
    for (int j = 0; j < 4; j++) {
        int n = tid + j * 256;
        float w[ADIM];
#pragma unroll
        for (int k = 0; k < ADIM; k++) w[k] = W[(size_t)k * HID + n];
        float bn = bias[n];
        for (int m = 0; m < TT; m++) {
            float acc = bn;
#pragma unroll
            for (int k = 0; k < ADIM; k++) acc += As[m * ADIM + k] * w[k];
            g_aemb[(size_t)(pos * TT + m) * HID + n] = tf32r(acc);
        }
    }
}

// ---------------- kernel 3: t2 = tau @ W2[1024:2048] + b2 (per category) ----------------
// grid (32 cats, 16 n-tiles of 64), 512 threads = 8 k-slices x 64 n-lanes
__global__ void t2_kernel(const float* __restrict__ W2w,
                          const float* __restrict__ W2bias) {
    __shared__ float tauS[8][HID];      // 32 KB
    __shared__ float red[8][8][64];     // 16 KB
    int c = blockIdx.x, nt = blockIdx.y;
    int lane = threadIdx.x & 63;
    int kg = threadIdx.x >> 6;          // 0..7
    int n = nt * 64 + lane;
    int s0 = g_seg_start[c], s1 = g_seg_start[c + 1];
    const float* Wb = W2w + ((size_t)c * 2048 + 1024) * HID;
    for (int p0 = s0; p0 < s1; p0 += 8) {
        int pc = s1 - p0; if (pc > 8) pc = 8;
        for (int i = threadIdx.x; i < 8 * HID; i += 512)
            tauS[i >> 10][i & 1023] =
                (i < pc * HID) ? g_tau[(size_t)(p0 + (i >> 10)) * HID + (i & 1023)] : 0.f;
        __syncthreads();
        float acc[8];
#pragma unroll
        for (int q = 0; q < 8; q++) acc[q] = 0.f;
        int kbeg = kg * 128;
        for (int k = kbeg; k < kbeg + 128; k += 8) {
            float w[8];
#pragma unroll
            for (int i = 0; i < 8; i++) w[i] = Wb[(size_t)(k + i) * HID + n];
#pragma unroll
            for (int i = 0; i < 8; i++)
#pragma unroll
                for (int q = 0; q < 8; q++) acc[q] += tauS[q][k + i] * w[i];
        }
#pragma unroll
        for (int q = 0; q < 8; q++) red[kg][q][lane] = acc[q];
        __syncthreads();
        if (kg == 0) {
            float bv = W2bias[(size_t)c * HID + n];
            for (int q = 0; q < pc; q++) {
                float v = bv;
#pragma unroll
                for (int s = 0; s < 8; s++) v += red[s][q][lane];
                g_t2[(size_t)(p0 + q) * HID + n] = v;
            }
        }
        __syncthreads();
    }
}

// ---------------- kernels 4/5: grouped tf32 GEMM, 4-stage cp.async pipeline ----------------
// BM=128, BN=128, KC=16, STAGES=4 (dynamic smem 75776 B), 2 CTAs/SM.
// GEMM2: A=g_aemb, B=W2w rows[0:1024], epi: +t2, silu -> g_h (tf32)
// GEMM3: A=g_h,    B=W3w,              epi: +b3, scatter -> out
#define GSTAGES 4
#define A_FLOATS (128 * 20)
#define B_FLOATS (16 * 136)
#define STAGE_A_OFF(s) ((s) * A_FLOATS)
#define STAGE_B_OFF(s) (GSTAGES * A_FLOATS + (s) * B_FLOATS)
#define GEMM_SMEM_BYTES (GSTAGES * (A_FLOATS + B_FLOATS) * 4)

template<bool GEMM2>
__global__ __launch_bounds__(256, 2)
void gemm_kernel(const float* __restrict__ Bbase,
                 size_t cat_stride,
                 const float* __restrict__ bias3,
                 float* __restrict__ out) {
    extern __shared__ float sm[];
    int mb = blockIdx.x;
    if (mb >= g_mb_count) return;
    const float* Ag = GEMM2 ? g_aemb : g_h;   // device-side symbol address
    int c = g_mb_cat[mb], mrow0 = g_mb_row[mb], m_rows = g_mb_rows[mb];
    int n0 = blockIdx.y * 128;
    const float* Bg = Bbase + (size_t)c * cat_stride;

    int tid = threadIdx.x, lane = tid & 31, wid = tid >> 5;
    int wm = wid >> 2, wn = wid & 3;    // 2 x 4 warp grid, warp tile 64x32
    int g = lane >> 2, tg = lane & 3;

    float acc[4][4][4];
#pragma unroll
    for (int a = 0; a < 4; a++)
#pragma unroll
        for (int b = 0; b < 4; b++)
#pragma unroll
            for (int i = 0; i < 4; i++) acc[a][b][i] = 0.f;

    auto load_stage = [&](int kt, int s) {
        int k0 = kt * 16;
        float* As = sm + STAGE_A_OFF(s);
        float* Bs = sm + STAGE_B_OFF(s);
#pragma unroll
        for (int i = 0; i < 2; i++) {           // A: 512 x 16B chunks
            int q = tid + i * 256;
            int row = q >> 2, c4 = (q & 3) * 4;
            cpasync16(&As[row * 20 + c4],
                      Ag + (size_t)(mrow0 + row) * HID + k0 + c4);
        }
#pragma unroll
        for (int i = 0; i < 2; i++) {           // B: 512 x 16B chunks
            int q = tid + i * 256;
            int kk = q >> 5, c4 = (q & 31) * 4;
            cpasync16(&Bs[kk * 136 + c4],
                      Bg + (size_t)(k0 + kk) * HID + n0 + c4);
        }
    };

    // prologue: stages 0..2 in flight
#pragma unroll
    for (int s = 0; s < GSTAGES - 1; s++) {
        load_stage(s, s);
        asm volatile("cp.async.commit_group;");
    }

    for (int kt = 0; kt < 64; kt++) {
        asm volatile("cp.async.wait_group %0;" :: "n"(GSTAGES - 2));
        __syncthreads();
        int buf = kt & (GSTAGES - 1);
        // issue next stage (or empty commit to keep group accounting in the tail)
        if (kt + GSTAGES - 1 < 64)
            load_stage(kt + GSTAGES - 1, (kt + GSTAGES - 1) & (GSTAGES - 1));
        asm volatile("cp.async.commit_group;");

        const float* As = sm + STAGE_A_OFF(buf);
        const float* Bs = sm + STAGE_B_OFF(buf);
#pragma unroll
        for (int ks = 0; ks < 2; ks++) {
            int kb = ks * 8;
            unsigned af[4][4];
#pragma unroll
            for (int fm = 0; fm < 4; fm++) {
                const float* ap = &As[(wm * 64 + fm * 16 + g) * 20 + kb + tg];
                af[fm][0] = __float_as_uint(ap[0]);
                af[fm][1] = __float_as_uint(ap[8 * 20]);
                af[fm][2] = __float_as_uint(ap[4]);
                af[fm][3] = __float_as_uint(ap[8 * 20 + 4]);
            }
            unsigned bfr[4][2];
#pragma unroll
            for (int fn = 0; fn < 4; fn++) {
                const float* bp = &Bs[(kb + tg) * 136 + wn * 32 + fn * 8 + g];
                bfr[fn][0] = tf32r_bits(bp[0]);
                bfr[fn][1] = tf32r_bits(bp[4 * 136]);
            }
#pragma unroll
            for (int fm = 0; fm < 4; fm++)
#pragma unroll
                for (int fn = 0; fn < 4; fn++)
                    mma_tf32(acc[fm][fn], af[fm], bfr[fn]);
        }
    }

    // epilogue
#pragma unroll
    for (int fm = 0; fm < 4; fm++)
#pragma unroll
        for (int fn = 0; fn < 4; fn++)
#pragma unroll
            for (int i = 0; i < 4; i++) {
                int row = wm * 64 + fm * 16 + g + ((i & 2) ? 8 : 0);
                if (row >= m_rows) continue;
                int col = n0 + wn * 32 + fn * 8 + tg * 2 + (i & 1);
                int R = mrow0 + row;
                float v = acc[fm][fn][i];
                if (GEMM2) {
                    v += g_t2[(size_t)(R >> 6) * HID + col];
                    v = v / (1.f + expf(-v));                 // silu
                    g_h[(size_t)R * HID + col] = tf32r(v);
                } else {
                    v += bias3[(size_t)c * HID + col];
                    int b = g_batch_of_pos[R >> 6];
                    out[((size_t)b * TT + (R & 63)) * HID + col] = v;
                }
            }
}

// ---------------- launch ----------------
extern "C" void kernel_launch(void* const* d_in, const int* in_sizes, int n_in,
                              void* d_out, int out_size) {
    const float* actions   = (const float*)d_in[0];
    const float* timesteps = (const float*)d_in[1];
    const float* W1w       = (const float*)d_in[2];
    const float* W1b       = (const float*)d_in[3];
    const float* W2w       = (const float*)d_in[4];
    const float* W2b       = (const float*)d_in[5];
    const float* W3w       = (const float*)d_in[6];
    const float* W3b       = (const float*)d_in[7];
    const int*   cats      = (const int*)d_in[8];
    float* out = (float*)d_out;

    cudaFuncSetAttribute(gemm_kernel<true>,
                         cudaFuncAttributeMaxDynamicSharedMemorySize, GEMM_SMEM_BYTES);
    cudaFuncSetAttribute(gemm_kernel<false>,
                         cudaFuncAttributeMaxDynamicSharedMemorySize, GEMM_SMEM_BYTES);

    setup_kernel<<<1, 128>>>(cats);
    tau_kernel<<<BB, 512>>>(timesteps);
    aemb_kernel<<<BB, 256>>>(actions, W1w, W1b, cats);
    t2_kernel<<<dim3(NUM_EMB, 16), 512>>>(W2w, W2b);
    gemm_kernel<true><<<dim3(96, 8), 256, GEMM_SMEM_BYTES>>>(W2w, (size_t)2048 * HID, nullptr, nullptr);
    gemm_kernel<false><<<dim3(96, 8), 256, GEMM_SMEM_BYTES>>>(W3w, (size_t)HID * HID, W3b, out);
}

// round 10
// speedup vs baseline: 1.1340x; 1.1340x over previous
#include <cuda_runtime.h>
#include <cuda_fp16.h>
#include <cstdint>

#define NUM_EMB 32
#define ADIM 32
#define HID 1024
#define BB 128
#define TT 64
#define ROWS_TOTAL (BB*TT)   /* 8192 grouped rows */

// ---------------- scratch (device globals; no allocs allowed) ----------------
__device__ __half g_aemb[(ROWS_TOTAL + 128) * HID]; // grouped a_emb (fp16), +pad rows (zero)
__device__ __half g_h   [(ROWS_TOTAL + 128) * HID]; // grouped hidden (fp16), +pad rows
__device__ float  g_tau [BB * HID];                 // grouped tau (fp32)
__device__ float  g_t2  [BB * HID];                 // grouped tau@W2b + b2 (fp32)
__device__ int    g_batch_of_pos[BB];
__device__ int    g_seg_start[NUM_EMB + 1];
__device__ int    g_mb_cat[128], g_mb_row[128], g_mb_rows[128];
__device__ int    g_mb_count;

// ---------------- helpers ----------------
__device__ __forceinline__ void cpasync16(void* dst, const void* src) {
    unsigned s = (unsigned)__cvta_generic_to_shared(dst);
    asm volatile("cp.async.cg.shared.global [%0], [%1], 16;" :: "r"(s), "l"(src));
}
// fp16 MMA, fp32 accumulate: D = A(16x16) * B(16x8) + D
__device__ __forceinline__ void mma_f16(float c[4], const unsigned a[4], const unsigned b[2]) {
    asm volatile(
        "mma.sync.aligned.m16n8k16.row.col.f32.f16.f16.f32 "
        "{%0,%1,%2,%3}, {%4,%5,%6,%7}, {%8,%9}, {%0,%1,%2,%3};"
        : "+f"(c[0]), "+f"(c[1]), "+f"(c[2]), "+f"(c[3])
        : "r"(a[0]), "r"(a[1]), "r"(a[2]), "r"(a[3]), "r"(b[0]), "r"(b[1]));
}

// ---------------- kernel 0: category grouping + mblock table (parallel) ----------------
__global__ void setup_kernel(const int* __restrict__ cats) {
    __shared__ int cnt[NUM_EMB], segs[NUM_EMB + 1], cur[NUM_EMB];
    int t = threadIdx.x;                 // 128 threads
    if (t < NUM_EMB) cnt[t] = 0;
    __syncthreads();
    int c = cats[t];                     // t in [0, BB)
    atomicAdd(&cnt[c], 1);
    __syncthreads();
    if (t == 0) {
        int s = 0;
        for (int i = 0; i < NUM_EMB; i++) { segs[i] = s; cur[i] = s; s += cnt[i]; }
        segs[NUM_EMB] = s;
    }
    __syncthreads();
    if (t <= NUM_EMB) g_seg_start[t] = segs[t];
    int p = atomicAdd(&cur[c], 1);       // order within a category is irrelevant
    g_batch_of_pos[p] = t;
    __syncthreads();
    if (t == 0) {
        int nmb = 0;
        for (int i = 0; i < NUM_EMB; i++) {
            int rows = cnt[i] * TT;
            int r0 = segs[i] * TT;
            for (int r = 0; r < rows; r += 128) {
                g_mb_cat[nmb] = i;
                g_mb_row[nmb] = r0 + r;
                g_mb_rows[nmb] = (rows - r < 128) ? (rows - r) : 128;
                nmb++;
            }
        }
        g_mb_count = nmb;
    }
}

// ---------------- kernel 1: tau (fp64 trig, grouped layout) ----------------
__global__ void tau_kernel(const float* __restrict__ ts) {
    int pos = blockIdx.x;
    int j = threadIdx.x;               // 0..511
    int b = g_batch_of_pos[pos];
    double t = (double)ts[b];
    double f = exp(-9.210340371976184 * ((double)j) / 512.0);
    double ph = t * f;
    g_tau[pos * HID + j]       = (float)sin(ph);
    g_tau[pos * HID + 512 + j] = (float)cos(ph);
}

// ---------------- kernel 2: a_emb = actions @ W1 + b1 (grouped, fp16 out) ----------------
__global__ void aemb_kernel(const float* __restrict__ actions,
                            const float* __restrict__ W1w,
                            const float* __restrict__ W1b,
                            const int*   __restrict__ cats) {
    __shared__ float As[TT * ADIM];
    int pos = blockIdx.x;
    int tid = threadIdx.x;             // 256 threads
    int b = g_batch_of_pos[pos];
    int c = cats[b];
    for (int i = tid; i < TT * ADIM; i += 256)
        As[i] = actions[b * TT * ADIM + i];
    __syncthreads();
    const float* W = W1w + (size_t)c * ADIM * HID;
    const float* bias = W1b + (size_t)c * HID;
    for (int j = 0; j < 4; j++) {
        int n = tid + j * 256;
        float w[ADIM];
#pragma unroll
        for (int k = 0; k < ADIM; k++) w[k] = W[(size_t)k * HID + n];
        float bn = bias[n];
        for (int m = 0; m < TT; m++) {
            float acc = bn;
#pragma unroll
            for (int k = 0; k < ADIM; k++) acc += As[m * ADIM + k] * w[k];
            g_aemb[(size_t)(pos * TT + m) * HID + n] = __float2half_rn(acc);
        }
    }
}

// ---------------- kernel 3: t2 = tau @ W2[1024:2048] + b2 (fp32, per category) ----------------
// grid (32 cats, 8 n-tiles), 512 threads = 4 k-slices x 128 n-lanes  (round-4 proven config)
__global__ void t2_kernel(const float* __restrict__ W2w,
                          const float* __restrict__ W2bias) {
    __shared__ float tauS[8][HID];      // 32 KB
    __shared__ float red[4][8][128];    // 16 KB
    int c = blockIdx.x, nt = blockIdx.y;
    int lane127 = threadIdx.x & 127;
    int kg = threadIdx.x >> 7;          // 0..3
    int n = nt * 128 + lane127;
    int s0 = g_seg_start[c], s1 = g_seg_start[c + 1];
    const float* Wb = W2w + ((size_t)c * 2048 + 1024) * HID;
    for (int p0 = s0; p0 < s1; p0 += 8) {
        int pc = s1 - p0; if (pc > 8) pc = 8;
        for (int i = threadIdx.x; i < 8 * HID; i += 512)
            tauS[i >> 10][i & 1023] =
                (i < pc * HID) ? g_tau[(size_t)(p0 + (i >> 10)) * HID + (i & 1023)] : 0.f;
        __syncthreads();
        float acc[8];
#pragma unroll
        for (int q = 0; q < 8; q++) acc[q] = 0.f;
        int kbeg = kg * 256;
        for (int k = kbeg; k < kbeg + 256; k += 8) {
            float w[8];
#pragma unroll
            for (int i = 0; i < 8; i++) w[i] = Wb[(size_t)(k + i) * HID + n];
#pragma unroll
            for (int i = 0; i < 8; i++)
#pragma unroll
                for (int q = 0; q < 8; q++) acc[q] += tauS[q][k + i] * w[i];
        }
#pragma unroll
        for (int q = 0; q < 8; q++) red[kg][q][lane127] = acc[q];
        __syncthreads();
        if (kg == 0) {
            float bv = W2bias[(size_t)c * HID + n];
            for (int q = 0; q < pc; q++) {
                float v = red[0][q][lane127] + red[1][q][lane127] +
                          red[2][q][lane127] + red[3][q][lane127] + bv;
                g_t2[(size_t)(p0 + q) * HID + n] = v;
            }
        }
        __syncthreads();
    }
}

// ---------------- kernels 4/5: grouped fp16 GEMM (mma.m16n8k16), BM=128 BN=128 KC=16 ----------------
// A (activations, fp16) via cp.async, smem [m][k] 12-word rows (8 data + 4 pad; bank-clean).
// B (= W transposed-on-load) smem [n][k] same geometry; fp32 LDG (coalesced) -> half2 STS.128.
// GEMM2: epi +t2, silu -> g_h (fp16).  GEMM3: epi +b3, scatter -> out (fp32).
#define AS_STRIDE 12                 /* 32-bit words per 16-half row */
#define TILE_WORDS (128 * AS_STRIDE) /* 1536 words = 6 KB per stage  */

template<bool GEMM2>
__global__ __launch_bounds__(256, 2)
void gemm_f16_kernel(const float* __restrict__ Bbase,
                     size_t cat_stride,
                     const float* __restrict__ bias3,
                     float* __restrict__ out) {
    __shared__ uint32_t As[2][TILE_WORDS];
    __shared__ uint32_t Bs[2][TILE_WORDS];

    int mb = blockIdx.x;
    if (mb >= g_mb_count) return;
    const __half* Ag = GEMM2 ? g_aemb : g_h;   // device-side symbol address
    int c = g_mb_cat[mb], mrow0 = g_mb_row[mb], m_rows = g_mb_rows[mb];
    int n0 = blockIdx.y * 128;
    const float* Bg = Bbase + (size_t)c * cat_stride;

    int tid = threadIdx.x, lane = tid & 31, wid = tid >> 5;
    int wm = wid >> 2, wn = wid & 3;    // 2 x 4 warp grid, warp tile 64x32
    int g = lane >> 2, tg = lane & 3;

    float acc[4][4][4];
#pragma unroll
    for (int a = 0; a < 4; a++)
#pragma unroll
        for (int b = 0; b < 4; b++)
#pragma unroll
            for (int i = 0; i < 4; i++) acc[a][b][i] = 0.f;

    // ---- loaders ----
    int rowA = tid >> 1, hsA = tid & 1;           // A: 256 x 16B chunks (8 halves each)
    auto load_A = [&](int kt, int buf) {
        cpasync16(&As[buf][rowA * AS_STRIDE + hsA * 4],
                  Ag + (size_t)(mrow0 + rowA) * HID + kt * 16 + hsA * 8);
    };
    int nB = tid & 127, khB = tid >> 7;           // B: each thread owns (n, 8 k-values)
    float br[8];
    auto ldg_B = [&](int kt) {
        const float* s = Bg + (size_t)(kt * 16 + khB * 8) * HID + n0 + nB;
#pragma unroll
        for (int i = 0; i < 8; i++) br[i] = s[(size_t)i * HID];
    };
    auto sts_B = [&](int buf) {                   // transposed, fp16-rounded, STS.128
        uint4 v;
        __half2 h0 = __floats2half2_rn(br[0], br[1]);
        __half2 h1 = __floats2half2_rn(br[2], br[3]);
        __half2 h2 = __floats2half2_rn(br[4], br[5]);
        __half2 h3 = __floats2half2_rn(br[6], br[7]);
        v.x = *(uint32_t*)&h0; v.y = *(uint32_t*)&h1;
        v.z = *(uint32_t*)&h2; v.w = *(uint32_t*)&h3;
        *(uint4*)&Bs[buf][nB * AS_STRIDE + khB * 4] = v;
    };

    // ---- prologue ----
    ldg_B(0);
    load_A(0, 0);
    asm volatile("cp.async.commit_group;");
    sts_B(0);
    asm volatile("cp.async.wait_group 0;");
    __syncthreads();

    // ---- main loop: 64 k-tiles of 16 ----
    for (int kt = 0; kt < 64; kt++) {
        int buf = kt & 1;
        if (kt + 1 < 64) {
            ldg_B(kt + 1);                        // gmem latency covered by compute below
            load_A(kt + 1, buf ^ 1);
            asm volatile("cp.async.commit_group;");
        }
        // fragments + 16 MMAs
        unsigned af[4][4], bf[4][2];
#pragma unroll
        for (int fm = 0; fm < 4; fm++) {
            const uint32_t* p = &As[buf][(wm * 64 + fm * 16 + g) * AS_STRIDE + tg];
            af[fm][0] = p[0];
            af[fm][1] = p[8 * AS_STRIDE];
            af[fm][2] = p[4];
            af[fm][3] = p[8 * AS_STRIDE + 4];
        }
#pragma unroll
        for (int fn = 0; fn < 4; fn++) {
            const uint32_t* p = &Bs[buf][(wn * 32 + fn * 8 + g) * AS_STRIDE + tg];
            bf[fn][0] = p[0];
            bf[fn][1] = p[4];
        }
#pragma unroll
        for (int fm = 0; fm < 4; fm++)
#pragma unroll
            for (int fn = 0; fn < 4; fn++)
                mma_f16(acc[fm][fn], af[fm], bf[fn]);

        if (kt + 1 < 64) {
            sts_B(buf ^ 1);
            asm volatile("cp.async.wait_group 0;");
        }
        __syncthreads();
    }

    // ---- epilogue: c0/c1 are adjacent columns -> paired stores ----
#pragma unroll
    for (int fm = 0; fm < 4; fm++)
#pragma unroll
        for (int fn = 0; fn < 4; fn++)
#pragma unroll
            for (int half = 0; half < 2; half++) {
                int row = wm * 64 + fm * 16 + g + half * 8;
                if (row >= m_rows) continue;
                int col = n0 + wn * 32 + fn * 8 + tg * 2;
                int R = mrow0 + row;
                float v0 = acc[fm][fn][half * 2 + 0];
                float v1 = acc[fm][fn][half * 2 + 1];
                if (GEMM2) {
                    const float* t2p = g_t2 + (size_t)(R >> 6) * HID + col;
                    v0 += t2p[0];  v0 = v0 / (1.f + expf(-v0));
                    v1 += t2p[1];  v1 = v1 / (1.f + expf(-v1));
                    __half2 h = __floats2half2_rn(v0, v1);
                    *(__half2*)(g_h + (size_t)R * HID + col) = h;
                } else {
                    const float* bp = bias3 + (size_t)c * HID + col;
                    int b = g_batch_of_pos[R >> 6];
                    float2 o = make_float2(v0 + bp[0], v1 + bp[1]);
                    *(float2*)(out + (size_t)(b * TT + (R & 63)) * HID + col) = o;
                }
            }
}

// ---------------- launch ----------------
extern "C" void kernel_launch(void* const* d_in, const int* in_sizes, int n_in,
                              void* d_out, int out_size) {
    const float* actions   = (const float*)d_in[0];
    const float* timesteps = (const float*)d_in[1];
    const float* W1w       = (const float*)d_in[2];
    const float* W1b       = (const float*)d_in[3];
    const float* W2w       = (const float*)d_in[4];
    const float* W2b       = (const float*)d_in[5];
    const float* W3w       = (const float*)d_in[6];
    const float* W3b       = (const float*)d_in[7];
    const int*   cats      = (const int*)d_in[8];
    float* out = (float*)d_out;

    setup_kernel<<<1, 128>>>(cats);
    tau_kernel<<<BB, 512>>>(timesteps);
    aemb_kernel<<<BB, 256>>>(actions, W1w, W1b, cats);
    t2_kernel<<<dim3(NUM_EMB, 8), 512>>>(W2w, W2b);
    gemm_f16_kernel<true><<<dim3(96, 8), 256>>>(W2w, (size_t)2048 * HID, nullptr, nullptr);
    gemm_f16_kernel<false><<<dim3(96, 8), 256>>>(W3w, (size_t)HID * HID, W3b, out);
}

// round 12
// speedup vs baseline: 1.3755x; 1.2129x over previous
#include <cuda_runtime.h>
#include <cuda_fp16.h>
#include <cstdint>

#define NUM_EMB 32
#define ADIM 32
#define HID 1024
#define BB 128
#define TT 64
#define ROWS_TOTAL (BB*TT)   /* 8192 grouped rows */

// ---------------- scratch (device globals; no allocs allowed) ----------------
__device__ __half g_h   [(ROWS_TOTAL + 128) * HID]; // grouped hidden (fp16), +pad rows (stay 0)
__device__ float  g_tau [BB * HID];                 // grouped tau (fp32)
__device__ float  g_t2  [BB * HID];                 // grouped tau@W2b + b2 (fp32)
__device__ float  g_w12 [NUM_EMB * ADIM * HID];     // fused W1@W2a per category (fp32)
__device__ float  g_v2  [NUM_EMB * HID];            // b1@W2a per category (fp32)
__device__ int    g_batch_of_pos[BB];
__device__ int    g_seg_start[NUM_EMB + 1];
__device__ int    g_mb_cat[128], g_mb_row[128], g_mb_rows[128];
__device__ int    g_mb_count;

// ---------------- helpers ----------------
__device__ __forceinline__ void cpasync16(void* dst, const void* src) {
    unsigned s = (unsigned)__cvta_generic_to_shared(dst);
    asm volatile("cp.async.cg.shared.global [%0], [%1], 16;" :: "r"(s), "l"(src));
}
// fp16 MMA, fp32 accumulate: D(16x8) += A(16x16) * B(16x8)
__device__ __forceinline__ void mma_f16(float c[4], const unsigned a[4], const unsigned b[2]) {
    asm volatile(
        "mma.sync.aligned.m16n8k16.row.col.f32.f16.f16.f32 "
        "{%0,%1,%2,%3}, {%4,%5,%6,%7}, {%8,%9}, {%0,%1,%2,%3};"
        : "+f"(c[0]), "+f"(c[1]), "+f"(c[2]), "+f"(c[3])
        : "r"(a[0]), "r"(a[1]), "r"(a[2]), "r"(a[3]), "r"(b[0]), "r"(b[1]));
}

// ---------------- kernel 0: category grouping + mblock table (parallel) ----------------
__global__ void setup_kernel(const int* __restrict__ cats) {
    __shared__ int cnt[NUM_EMB], segs[NUM_EMB + 1], cur[NUM_EMB];
    int t = threadIdx.x;                 // 128 threads
    if (t < NUM_EMB) cnt[t] = 0;
    __syncthreads();
    int c = cats[t];                     // t in [0, BB)
    atomicAdd(&cnt[c], 1);
    __syncthreads();
    if (t == 0) {
        int s = 0;
        for (int i = 0; i < NUM_EMB; i++) { segs[i] = s; cur[i] = s; s += cnt[i]; }
        segs[NUM_EMB] = s;
    }
    __syncthreads();
    if (t <= NUM_EMB) g_seg_start[t] = segs[t];
    int p = atomicAdd(&cur[c], 1);
    g_batch_of_pos[p] = t;
    __syncthreads();
    if (t == 0) {
        int nmb = 0;
        for (int i = 0; i < NUM_EMB; i++) {
            int rows = cnt[i] * TT;
            int r0 = segs[i] * TT;
            for (int r = 0; r < rows; r += 128) {
                g_mb_cat[nmb] = i;
                g_mb_row[nmb] = r0 + r;
                g_mb_rows[nmb] = (rows - r < 128) ? (rows - r) : 128;
                nmb++;
            }
        }
        g_mb_count = nmb;
    }
}

// ---------------- kernel 1: tau (fp64 trig, grouped layout) ----------------
__global__ void tau_kernel(const float* __restrict__ ts) {
    int pos = blockIdx.x;
    int j = threadIdx.x;               // 0..511
    int b = g_batch_of_pos[pos];
    double t = (double)ts[b];
    double f = exp(-9.210340371976184 * ((double)j) / 512.0);
    double ph = t * f;
    g_tau[pos * HID + j]       = (float)sin(ph);
    g_tau[pos * HID + 512 + j] = (float)cos(ph);
}

// ---------------- kernel 2: W12[c] = [W1[c]; b1[c]] @ W2a[c]  (fp16 tensor, streamed) ----------------
// A = 48x16 fp16 tile per k-step: rows 0..31 = W1[c], row 32 = b1[c], rows 33..47 = 0.
// B = W2a chunk transposed-on-load to [n][k] fp16 (same pattern as main GEMM).
// Output: g_w12[c][a][n] (a<32), g_v2[c][n] (a==32). 8 warps, each N=16 slice, M=48.
#define WS 12   /* 32-bit words per 16-half row */
__global__ __launch_bounds__(256)
void w12_kernel(const float* __restrict__ W1w,
                const float* __restrict__ W1b,
                const float* __restrict__ W2w) {
    __shared__ uint32_t As[2][48 * WS];
    __shared__ uint32_t Bs[2][128 * WS];
    int c = blockIdx.x, n0 = blockIdx.y * 128;
    int tid = threadIdx.x, lane = tid & 31, wid = tid >> 5;
    int g = lane >> 2, tg = lane & 3;
    int nw0 = wid * 16;
    const float* W1 = W1w + (size_t)c * ADIM * HID;
    const float* b1 = W1b + (size_t)c * HID;
    const float* Bg = W2w + (size_t)c * 2048 * HID;     // rows [0,1024) = W2a

    // zero pad rows 33..47 of both A buffers (read by MMA, must be 0)
    for (int i = tid; i < 2 * 15 * WS; i += 256) {
        int bu = i / (15 * WS), r = i % (15 * WS);
        As[bu][33 * WS + r] = 0;
    }

    float acc[3][2][4];
#pragma unroll
    for (int a = 0; a < 3; a++)
#pragma unroll
        for (int b = 0; b < 2; b++)
#pragma unroll
            for (int i = 0; i < 4; i++) acc[a][b][i] = 0.f;

    float4 ar;                                    // A chunk regs (tid<132)
    auto ldgA = [&](int kt) {
        if (tid < 132) {
            int a = tid >> 2, q = tid & 3;
            const float* src = (a < 32 ? W1 + (size_t)a * HID : b1) + kt * 16 + q * 4;
            ar = *(const float4*)src;
        }
    };
    auto stsA = [&](int buf) {
        if (tid < 132) {
            int a = tid >> 2, q = tid & 3;
            __half2 h0 = __floats2half2_rn(ar.x, ar.y);
            __half2 h1 = __floats2half2_rn(ar.z, ar.w);
            As[buf][a * WS + q * 2]     = *(uint32_t*)&h0;
            As[buf][a * WS + q * 2 + 1] = *(uint32_t*)&h1;
        }
    };
    int nB = tid & 127, khB = tid >> 7;           // B: thread owns (n, 8 k-values)
    float br[8];
    auto ldgB = [&](int kt) {
        const float* s = Bg + (size_t)(kt * 16 + khB * 8) * HID + n0 + nB;
#pragma unroll
        for (int i = 0; i < 8; i++) br[i] = s[(size_t)i * HID];
    };
    auto stsB = [&](int buf) {
        uint4 v;
        __half2 h0 = __floats2half2_rn(br[0], br[1]);
        __half2 h1 = __floats2half2_rn(br[2], br[3]);
        __half2 h2 = __floats2half2_rn(br[4], br[5]);
        __half2 h3 = __floats2half2_rn(br[6], br[7]);
        v.x = *(uint32_t*)&h0; v.y = *(uint32_t*)&h1;
        v.z = *(uint32_t*)&h2; v.w = *(uint32_t*)&h3;
        *(uint4*)&Bs[buf][nB * WS + khB * 4] = v;
    };

    ldgB(0); ldgA(0);
    stsB(0); stsA(0);
    __syncthreads();

    for (int kt = 0; kt < 64; kt++) {
        int buf = kt & 1;
        if (kt + 1 < 64) { ldgB(kt + 1); ldgA(kt + 1); }

        unsigned af[3][4], bf[2][2];
#pragma unroll
        for (int fm = 0; fm < 3; fm++) {
            const uint32_t* p = &As[buf][(fm * 16 + g) * WS + tg];
            af[fm][0] = p[0];
            af[fm][1] = p[8 * WS];
            af[fm][2] = p[4];
            af[fm][3] = p[8 * WS + 4];
        }
#pragma unroll
        for (int fn = 0; fn < 2; fn++) {
            const uint32_t* p = &Bs[buf][(nw0 + fn * 8 + g) * WS + tg];
            bf[fn][0] = p[0];
            bf[fn][1] = p[4];
        }
#pragma unroll
        for (int fm = 0; fm < 3; fm++)
#pragma unroll
            for (int fn = 0; fn < 2; fn++)
                mma_f16(acc[fm][fn], af[fm], bf[fn]);

        if (kt + 1 < 64) { stsB(buf ^ 1); stsA(buf ^ 1); }
        __syncthreads();
    }

    // epilogue: rows<32 -> g_w12; row 32 -> g_v2 (b2 is added later, in t2)
#pragma unroll
    for (int fm = 0; fm < 3; fm++)
#pragma unroll
        for (int fn = 0; fn < 2; fn++)
#pragma unroll
            for (int hf = 0; hf < 2; hf++) {
                int row = fm * 16 + g + hf * 8;
                int col = n0 + nw0 + fn * 8 + tg * 2;
                float v0 = acc[fm][fn][hf * 2 + 0];
                float v1 = acc[fm][fn][hf * 2 + 1];
                if (row < 32) {
                    *(float2*)&g_w12[(size_t)(c * ADIM + row) * HID + col] = make_float2(v0, v1);
                } else if (row == 32) {
                    *(float2*)&g_v2[(size_t)c * HID + col] = make_float2(v0, v1);
                }
            }
}

// ---------------- kernel 3: t2 = tau @ W2b + b2 (fp32, per category; proven config) ----------------
__global__ void t2_kernel(const float* __restrict__ W2w,
                          const float* __restrict__ W2bias) {
    __shared__ float tauS[8][HID];      // 32 KB
    __shared__ float red[4][8][128];    // 16 KB
    int c = blockIdx.x, nt = blockIdx.y;
    int lane127 = threadIdx.x & 127;
    int kg = threadIdx.x >> 7;          // 0..3
    int n = nt * 128 + lane127;
    int s0 = g_seg_start[c], s1 = g_seg_start[c + 1];
    const float* Wb = W2w + ((size_t)c * 2048 + 1024) * HID;
    for (int p0 = s0; p0 < s1; p0 += 8) {
        int pc = s1 - p0; if (pc > 8) pc = 8;
        for (int i = threadIdx.x; i < 8 * HID; i += 512)
            tauS[i >> 10][i & 1023] =
                (i < pc * HID) ? g_tau[(size_t)(p0 + (i >> 10)) * HID + (i & 1023)] : 0.f;
        __syncthreads();
        float acc[8];
#pragma unroll
        for (int q = 0; q < 8; q++) acc[q] = 0.f;
        int kbeg = kg * 256;
        for (int k = kbeg; k < kbeg + 256; k += 8) {
            float w[8];
#pragma unroll
            for (int i = 0; i < 8; i++) w[i] = Wb[(size_t)(k + i) * HID + n];
#pragma unroll
            for (int i = 0; i < 8; i++)
#pragma unroll
                for (int q = 0; q < 8; q++) acc[q] += tauS[q][k + i] * w[i];
        }
#pragma unroll
        for (int q = 0; q < 8; q++) red[kg][q][lane127] = acc[q];
        __syncthreads();
        if (kg == 0) {
            float bv = W2bias[(size_t)c * HID + n];
            for (int q = 0; q < pc; q++) {
                float v = red[0][q][lane127] + red[1][q][lane127] +
                          red[2][q][lane127] + red[3][q][lane127] + bv;
                g_t2[(size_t)(p0 + q) * HID + n] = v;
            }
        }
        __syncthreads();
    }
}

// ---------------- kernel 4: hidden = silu(actions @ W12 + v2 + t2) -> g_h fp16 ----------------
// K=32 SIMT GEMM (the proven aemb shape), actions in raw fp32.
__global__ void gemm2s_kernel(const float* __restrict__ actions,
                              const int*   __restrict__ cats) {
    __shared__ float Xs[TT * ADIM];
    int pos = blockIdx.x;
    int tid = threadIdx.x;             // 256 threads
    int b = g_batch_of_pos[pos];
    int c = cats[b];
    for (int i = tid; i < TT * ADIM; i += 256)
        Xs[i] = actions[b * TT * ADIM + i];
    __syncthreads();
    const float* W = g_w12 + (size_t)c * ADIM * HID;
    for (int j = 0; j < 4; j++) {
        int n = tid + j * 256;
        float w[ADIM];
#pragma unroll
        for (int k = 0; k < ADIM; k++) w[k] = W[(size_t)k * HID + n];
        float bn = g_v2[(size_t)c * HID + n] + g_t2[(size_t)pos * HID + n];
        for (int m = 0; m < TT; m++) {
            float acc = bn;
#pragma unroll
            for (int k = 0; k < ADIM; k++) acc += Xs[m * ADIM + k] * w[k];
            float v = acc / (1.f + expf(-acc));               // silu
            g_h[(size_t)(pos * TT + m) * HID + n] = __float2half_rn(v);
        }
    }
}

// ---------------- kernel 5: out = g_h @ W3 + b3 (fp16 tensor GEMM, scatter) ----------------
#define AS_STRIDE 12
#define TILE_WORDS (128 * AS_STRIDE)

__global__ __launch_bounds__(256, 2)
void gemm3_kernel(const float* __restrict__ Bbase,
                  const float* __restrict__ bias3,
                  float* __restrict__ out) {
    __shared__ uint32_t As[2][TILE_WORDS];
    __shared__ uint32_t Bs[2][TILE_WORDS];

    int mb = blockIdx.x;
    if (mb >= g_mb_count) return;
    const __half* Ag = g_h;
    int c = g_mb_cat[mb], mrow0 = g_mb_row[mb], m_rows = g_mb_rows[mb];
    int n0 = blockIdx.y * 128;
    const float* Bg = Bbase + (size_t)c * HID * HID;

    int tid = threadIdx.x, lane = tid & 31, wid = tid >> 5;
    int wm = wid >> 2, wn = wid & 3;    // 2 x 4 warp grid, warp tile 64x32
    int g = lane >> 2, tg = lane & 3;

    float acc[4][4][4];
#pragma unroll
    for (int a = 0; a < 4; a++)
#pragma unroll
        for (int b = 0; b < 4; b++)
#pragma unroll
            for (int i = 0; i < 4; i++) acc[a][b][i] = 0.f;

    int rowA = tid >> 1, hsA = tid & 1;
    auto load_A = [&](int kt, int buf) {
        cpasync16(&As[buf][rowA * AS_STRIDE + hsA * 4],
                  Ag + (size_t)(mrow0 + rowA) * HID + kt * 16 + hsA * 8);
    };
    int nB = tid & 127, khB = tid >> 7;
    float br[8];
    auto ldg_B = [&](int kt) {
        const float* s = Bg + (size_t)(kt * 16 + khB * 8) * HID + n0 + nB;
#pragma unroll
        for (int i = 0; i < 8; i++) br[i] = s[(size_t)i * HID];
    };
    auto sts_B = [&](int buf) {
        uint4 v;
        __half2 h0 = __floats2half2_rn(br[0], br[1]);
        __half2 h1 = __floats2half2_rn(br[2], br[3]);
        __half2 h2 = __floats2half2_rn(br[4], br[5]);
        __half2 h3 = __floats2half2_rn(br[6], br[7]);
        v.x = *(uint32_t*)&h0; v.y = *(uint32_t*)&h1;
        v.z = *(uint32_t*)&h2; v.w = *(uint32_t*)&h3;
        *(uint4*)&Bs[buf][nB * AS_STRIDE + khB * 4] = v;
    };

    ldg_B(0);
    load_A(0, 0);
    asm volatile("cp.async.commit_group;");
    sts_B(0);
    asm volatile("cp.async.wait_group 0;");
    __syncthreads();

    for (int kt = 0; kt < 64; kt++) {
        int buf = kt & 1;
        if (kt + 1 < 64) {
            ldg_B(kt + 1);
            load_A(kt + 1, buf ^ 1);
            asm volatile("cp.async.commit_group;");
        }
        unsigned af[4][4], bf[4][2];
#pragma unroll
        for (int fm = 0; fm < 4; fm++) {
            const uint32_t* p = &As[buf][(wm * 64 + fm * 16 + g) * AS_STRIDE + tg];
            af[fm][0] = p[0];
            af[fm][1] = p[8 * AS_STRIDE];
            af[fm][2] = p[4];
            af[fm][3] = p[8 * AS_STRIDE + 4];
        }
#pragma unroll
        for (int fn = 0; fn < 4; fn++) {
            const uint32_t* p = &Bs[buf][(wn * 32 + fn * 8 + g) * AS_STRIDE + tg];
            bf[fn][0] = p[0];
            bf[fn][1] = p[4];
        }
#pragma unroll
        for (int fm = 0; fm < 4; fm++)
#pragma unroll
            for (int fn = 0; fn < 4; fn++)
                mma_f16(acc[fm][fn], af[fm], bf[fn]);

        if (kt + 1 < 64) {
            sts_B(buf ^ 1);
            asm volatile("cp.async.wait_group 0;");
        }
        __syncthreads();
    }

#pragma unroll
    for (int fm = 0; fm < 4; fm++)
#pragma unroll
        for (int fn = 0; fn < 4; fn++)
#pragma unroll
            for (int hf = 0; hf < 2; hf++) {
                int row = wm * 64 + fm * 16 + g + hf * 8;
                if (row >= m_rows) continue;
                int col = n0 + wn * 32 + fn * 8 + tg * 2;
                int R = mrow0 + row;
                float v0 = acc[fm][fn][hf * 2 + 0];
                float v1 = acc[fm][fn][hf * 2 + 1];
                const float* bp = bias3 + (size_t)c * HID + col;
                int b = g_batch_of_pos[R >> 6];
                float2 o = make_float2(v0 + bp[0], v1 + bp[1]);
                *(float2*)(out + (size_t)(b * TT + (R & 63)) * HID + col) = o;
            }
}

// ---------------- launch ----------------
extern "C" void kernel_launch(void* const* d_in, const int* in_sizes, int n_in,
                              void* d_out, int out_size) {
    const float* actions   = (const float*)d_in[0];
    const float* timesteps = (const float*)d_in[1];
    const float* W1w       = (const float*)d_in[2];
    const float* W1b       = (const float*)d_in[3];
    const float* W2w       = (const float*)d_in[4];
    const float* W2b       = (const float*)d_in[5];
    const float* W3w       = (const float*)d_in[6];
    const float* W3b       = (const float*)d_in[7];
    const int*   cats      = (const int*)d_in[8];
    float* out = (float*)d_out;

    setup_kernel<<<1, 128>>>(cats);
    tau_kernel<<<BB, 512>>>(timesteps);
    w12_kernel<<<dim3(NUM_EMB, 8), 256>>>(W1w, W1b, W2w);
    t2_kernel<<<dim3(NUM_EMB, 8), 512>>>(W2w, W2b);
    gemm2s_kernel<<<BB, 256>>>(actions, cats);
    gemm3_kernel<<<dim3(96, 8), 256>>>(W3w, W3b, out);
}

// round 14
// speedup vs baseline: 1.4042x; 1.0209x over previous
#include <cuda_runtime.h>
#include <cuda_fp16.h>
#include <cstdint>

#define NUM_EMB 32
#define ADIM 32
#define HID 1024
#define BB 128
#define TT 64
#define ROWS_TOTAL (BB*TT)   /* 8192 grouped rows */

// ---------------- scratch (device globals; no allocs allowed) ----------------
__device__ __half g_h   [(ROWS_TOTAL + 128) * HID]; // grouped hidden (fp16), +pad rows (stay 0)
__device__ float  g_tau [BB * HID];                 // grouped tau (fp32)
__device__ float  g_t2  [BB * HID];                 // grouped tau@W2b + b2 (fp32)
__device__ float  g_w12 [NUM_EMB * ADIM * HID];     // fused W1@W2a per category (fp32)
__device__ float  g_v2  [NUM_EMB * HID];            // b1@W2a per category (fp32)
__device__ int    g_batch_of_pos[BB];
__device__ int    g_seg_start[NUM_EMB + 1];
__device__ int    g_mb_cat[128], g_mb_row[128], g_mb_rows[128];
__device__ int    g_mb_count;

// ---------------- helpers ----------------
__device__ __forceinline__ void cpasync16(void* dst, const void* src) {
    unsigned s = (unsigned)__cvta_generic_to_shared(dst);
    asm volatile("cp.async.cg.shared.global [%0], [%1], 16;" :: "r"(s), "l"(src));
}
// fp16 MMA, fp32 accumulate: D(16x8) += A(16x16) * B(16x8)
__device__ __forceinline__ void mma_f16(float c[4], const unsigned a[4], const unsigned b[2]) {
    asm volatile(
        "mma.sync.aligned.m16n8k16.row.col.f32.f16.f16.f32 "
        "{%0,%1,%2,%3}, {%4,%5,%6,%7}, {%8,%9}, {%0,%1,%2,%3};"
        : "+f"(c[0]), "+f"(c[1]), "+f"(c[2]), "+f"(c[3])
        : "r"(a[0]), "r"(a[1]), "r"(a[2]), "r"(a[3]), "r"(b[0]), "r"(b[1]));
}

// ---------------- kernel 0: category grouping + mblock table (parallel) ----------------
__global__ void setup_kernel(const int* __restrict__ cats) {
    __shared__ int cnt[NUM_EMB], segs[NUM_EMB + 1], cur[NUM_EMB];
    int t = threadIdx.x;                 // 128 threads
    if (t < NUM_EMB) cnt[t] = 0;
    __syncthreads();
    int c = cats[t];                     // t in [0, BB)
    atomicAdd(&cnt[c], 1);
    __syncthreads();
    if (t == 0) {
        int s = 0;
        for (int i = 0; i < NUM_EMB; i++) { segs[i] = s; cur[i] = s; s += cnt[i]; }
        segs[NUM_EMB] = s;
    }
    __syncthreads();
    if (t <= NUM_EMB) g_seg_start[t] = segs[t];
    int p = atomicAdd(&cur[c], 1);
    g_batch_of_pos[p] = t;
    __syncthreads();
    if (t == 0) {
        int nmb = 0;
        for (int i = 0; i < NUM_EMB; i++) {
            int rows = cnt[i] * TT;
            int r0 = segs[i] * TT;
            for (int r = 0; r < rows; r += 128) {
                g_mb_cat[nmb] = i;
                g_mb_row[nmb] = r0 + r;
                g_mb_rows[nmb] = (rows - r < 128) ? (rows - r) : 128;
                nmb++;
            }
        }
        g_mb_count = nmb;
    }
}

// ---------------- kernel 1: tau (fp64 trig, grouped layout) ----------------
__global__ void tau_kernel(const float* __restrict__ ts) {
    int pos = blockIdx.x;
    int j = threadIdx.x;               // 0..511
    int b = g_batch_of_pos[pos];
    double t = (double)ts[b];
    double f = exp(-9.210340371976184 * ((double)j) / 512.0);
    double ph = t * f;
    g_tau[pos * HID + j]       = (float)sin(ph);
    g_tau[pos * HID + 512 + j] = (float)cos(ph);
}

// ---------------- kernel 2: fused W2 streamer ----------------
// blocks [0,512):   w12 part — W12[c] = [W1[c]; b1[c]] @ W2a[c], n-tiles of 64 (fp16 MMA)
// blocks [512,1024): t2 part — t2 = tau @ W2b[c] + b2, n-tiles of 64 (SIMT fp32)
// Both families stream disjoint 256KB W2 slices exactly once; running them in one
// launch fills the chip (~740 resident CTAs) so the combined 256 MB goes at full HBM rate.
#define WS 12   /* 32-bit words per 16-half row */
__global__ __launch_bounds__(256)
void stream_kernel(const float* __restrict__ W1w,
                   const float* __restrict__ W1b,
                   const float* __restrict__ W2w,
                   const float* __restrict__ W2bias) {
    __shared__ float smem_f[10240];      // 40 KB, shared by both parts
    int bid = blockIdx.x;
    int tid = threadIdx.x;

    if (bid < 512) {
        // ================= w12 part =================
        uint32_t* As = (uint32_t*)smem_f;            // 2 x 48 x WS = 1152 words
        uint32_t* Bs = (uint32_t*)smem_f + 1152;     // 2 x 64 x WS = 1536 words
        int c = bid >> 4, n0 = (bid & 15) * 64;
        int lane = tid & 31, wid = tid >> 5;
        int g = lane >> 2, tg = lane & 3;
        int nw0 = wid * 8;                           // warp's 8-column slice
        const float* W1 = W1w + (size_t)c * ADIM * HID;
        const float* b1 = W1b + (size_t)c * HID;
        const float* Bg = W2w + (size_t)c * 2048 * HID;   // rows [0,1024) = W2a

        // zero A pad rows 33..47 (read by MMA as zeros) in both buffers
        for (int i = tid; i < 2 * 15 * WS; i += 256) {
            int bu = i / (15 * WS), r = i % (15 * WS);
            As[bu * 48 * WS + 33 * WS + r] = 0;
        }

        float acc[3][4];
#pragma unroll
        for (int a = 0; a < 3; a++)
#pragma unroll
            for (int i = 0; i < 4; i++) acc[a][i] = 0.f;

        float4 ar;                                   // A regs (tid<132)
        auto ldgA = [&](int kt) {
            if (tid < 132) {
                int a = tid >> 2, q = tid & 3;
                const float* src = (a < 32 ? W1 + (size_t)a * HID : b1) + kt * 16 + q * 4;
                ar = *(const float4*)src;
            }
        };
        auto stsA = [&](int buf) {
            if (tid < 132) {
                int a = tid >> 2, q = tid & 3;
                __half2 h0 = __floats2half2_rn(ar.x, ar.y);
                __half2 h1 = __floats2half2_rn(ar.z, ar.w);
                As[buf * 48 * WS + a * WS + q * 2]     = *(uint32_t*)&h0;
                As[buf * 48 * WS + a * WS + q * 2 + 1] = *(uint32_t*)&h1;
            }
        };
        int nB = tid & 63, kqB = tid >> 6;           // thread owns (n, 4 k-values)
        float br[4];
        auto ldgB = [&](int kt) {
            const float* s = Bg + (size_t)(kt * 16 + kqB * 4) * HID + n0 + nB;
#pragma unroll
            for (int i = 0; i < 4; i++) br[i] = s[(size_t)i * HID];
        };
        auto stsB = [&](int buf) {
            __half2 h0 = __floats2half2_rn(br[0], br[1]);
            __half2 h1 = __floats2half2_rn(br[2], br[3]);
            uint2 v; v.x = *(uint32_t*)&h0; v.y = *(uint32_t*)&h1;
            *(uint2*)&Bs[buf * 64 * WS + nB * WS + kqB * 2] = v;
        };

        ldgB(0); ldgA(0);
        stsB(0); stsA(0);
        __syncthreads();

        for (int kt = 0; kt < 64; kt++) {
            int buf = kt & 1;
            if (kt + 1 < 64) { ldgB(kt + 1); ldgA(kt + 1); }

            unsigned af[3][4], bf[2];
#pragma unroll
            for (int fm = 0; fm < 3; fm++) {
                const uint32_t* p = &As[buf * 48 * WS + (fm * 16 + g) * WS + tg];
                af[fm][0] = p[0];
                af[fm][1] = p[8 * WS];
                af[fm][2] = p[4];
                af[fm][3] = p[8 * WS + 4];
            }
            {
                const uint32_t* p = &Bs[buf * 64 * WS + (nw0 + g) * WS + tg];
                bf[0] = p[0];
                bf[1] = p[4];
            }
#pragma unroll
            for (int fm = 0; fm < 3; fm++)
                mma_f16(acc[fm], af[fm], bf);

            if (kt + 1 < 64) { stsB(buf ^ 1); stsA(buf ^ 1); }
            __syncthreads();
        }

        // epilogue: rows<32 -> g_w12; row 32 -> g_v2
#pragma unroll
        for (int fm = 0; fm < 3; fm++)
#pragma unroll
            for (int hf = 0; hf < 2; hf++) {
                int row = fm * 16 + g + hf * 8;
                int col = n0 + nw0 + tg * 2;
                float v0 = acc[fm][hf * 2 + 0];
                float v1 = acc[fm][hf * 2 + 1];
                if (row < 32) {
                    *(float2*)&g_w12[(size_t)(c * ADIM + row) * HID + col] = make_float2(v0, v1);
                } else if (row == 32) {
                    *(float2*)&g_v2[(size_t)c * HID + col] = make_float2(v0, v1);
                }
            }
    } else {
        // ================= t2 part =================
        float (*tauS)[HID] = (float(*)[HID])smem_f;                  // 8 x 1024
        float (*red)[8][64] = (float(*)[8][64])(smem_f + 8192);      // 4 x 8 x 64
        int idx = bid - 512;
        int c = idx >> 4, nt = idx & 15;
        int lane = tid & 63;
        int kg = tid >> 6;               // 0..3 (k-slices of 256)
        int n = nt * 64 + lane;
        int s0 = g_seg_start[c], s1 = g_seg_start[c + 1];
        const float* Wb = W2w + ((size_t)c * 2048 + 1024) * HID;
        for (int p0 = s0; p0 < s1; p0 += 8) {
            int pc = s1 - p0; if (pc > 8) pc = 8;
            for (int i = tid; i < 8 * HID; i += 256)
                tauS[i >> 10][i & 1023] =
                    (i < pc * HID) ? g_tau[(size_t)(p0 + (i >> 10)) * HID + (i & 1023)] : 0.f;
            __syncthreads();
            float acc[8];
#pragma unroll
            for (int q = 0; q < 8; q++) acc[q] = 0.f;
            int kbeg = kg * 256;
            for (int k = kbeg; k < kbeg + 256; k += 8) {
                float w[8];
#pragma unroll
                for (int i = 0; i < 8; i++) w[i] = Wb[(size_t)(k + i) * HID + n];
#pragma unroll
                for (int i = 0; i < 8; i++)
#pragma unroll
                    for (int q = 0; q < 8; q++) acc[q] += tauS[q][k + i] * w[i];
            }
#pragma unroll
            for (int q = 0; q < 8; q++) red[kg][q][lane] = acc[q];
            __syncthreads();
            if (kg == 0) {
                float bv = W2bias[(size_t)c * HID + n];
                for (int q = 0; q < pc; q++) {
                    float v = red[0][q][lane] + red[1][q][lane] +
                              red[2][q][lane] + red[3][q][lane] + bv;
                    g_t2[(size_t)(p0 + q) * HID + n] = v;
                }
            }
            __syncthreads();
        }
    }
}

// ---------------- kernel 3: hidden = silu(actions @ W12 + v2 + t2) -> g_h fp16 ----------------
__global__ void gemm2s_kernel(const float* __restrict__ actions,
                              const int*   __restrict__ cats) {
    __shared__ float Xs[TT * ADIM];
    int pos = blockIdx.x;
    int tid = threadIdx.x;             // 256 threads
    int b = g_batch_of_pos[pos];
    int c = cats[b];
    for (int i = tid; i < TT * ADIM; i += 256)
        Xs[i] = actions[b * TT * ADIM + i];
    __syncthreads();
    const float* W = g_w12 + (size_t)c * ADIM * HID;
    for (int j = 0; j < 4; j++) {
        int n = tid + j * 256;
        float w[ADIM];
#pragma unroll
        for (int k = 0; k < ADIM; k++) w[k] = W[(size_t)k * HID + n];
        float bn = g_v2[(size_t)c * HID + n] + g_t2[(size_t)pos * HID + n];
        for (int m = 0; m < TT; m++) {
            float acc = bn;
#pragma unroll
            for (int k = 0; k < ADIM; k++) acc += Xs[m * ADIM + k] * w[k];
            float v = acc / (1.f + expf(-acc));               // silu
            g_h[(size_t)(pos * TT + m) * HID + n] = __float2half_rn(v);
        }
    }
}

// ---------------- kernel 4: out = g_h @ W3 + b3 (fp16 tensor GEMM, scatter) ----------------
#define AS_STRIDE 12
#define TILE_WORDS (128 * AS_STRIDE)

__global__ __launch_bounds__(256, 2)
void gemm3_kernel(const float* __restrict__ Bbase,
                  const float* __restrict__ bias3,
                  float* __restrict__ out) {
    __shared__ uint32_t As[2][TILE_WORDS];
    __shared__ uint32_t Bs[2][TILE_WORDS];

    int mb = blockIdx.x;
    if (mb >= g_mb_count) return;
    const __half* Ag = g_h;
    int c = g_mb_cat[mb], mrow0 = g_mb_row[mb], m_rows = g_mb_rows[mb];
    int n0 = blockIdx.y * 128;
    const float* Bg = Bbase + (size_t)c * HID * HID;

    int tid = threadIdx.x, lane = tid & 31, wid = tid >> 5;
    int wm = wid >> 2, wn = wid & 3;    // 2 x 4 warp grid, warp tile 64x32
    int g = lane >> 2, tg = lane & 3;

    float acc[4][4][4];
#pragma unroll
    for (int a = 0; a < 4; a++)
#pragma unroll
        for (int b = 0; b < 4; b++)
#pragma unroll
            for (int i = 0; i < 4; i++) acc[a][b][i] = 0.f;

    int rowA = tid >> 1, hsA = tid & 1;
    auto load_A = [&](int kt, int buf) {
        cpasync16(&As[buf][rowA * AS_STRIDE + hsA * 4],
                  Ag + (size_t)(mrow0 + rowA) * HID + kt * 16 + hsA * 8);
    };
    int nB = tid & 127, khB = tid >> 7;
    float br[8];
    auto ldg_B = [&](int kt) {
        const float* s = Bg + (size_t)(kt * 16 + khB * 8) * HID + n0 + nB;
#pragma unroll
        for (int i = 0; i < 8; i++) br[i] = s[(size_t)i * HID];
    };
    auto sts_B = [&](int buf) {
        uint4 v;
        __half2 h0 = __floats2half2_rn(br[0], br[1]);
        __half2 h1 = __floats2half2_rn(br[2], br[3]);
        __half2 h2 = __floats2half2_rn(br[4], br[5]);
        __half2 h3 = __floats2half2_rn(br[6], br[7]);
        v.x = *(uint32_t*)&h0; v.y = *(uint32_t*)&h1;
        v.z = *(uint32_t*)&h2; v.w = *(uint32_t*)&h3;
        *(uint4*)&Bs[buf][nB * AS_STRIDE + khB * 4] = v;
    };

    ldg_B(0);
    load_A(0, 0);
    asm volatile("cp.async.commit_group;");
    sts_B(0);
    asm volatile("cp.async.wait_group 0;");
    __syncthreads();

    for (int kt = 0; kt < 64; kt++) {
        int buf = kt & 1;
        if (kt + 1 < 64) {
            ldg_B(kt + 1);
            load_A(kt + 1, buf ^ 1);
            asm volatile("cp.async.commit_group;");
        }
        unsigned af[4][4], bf[4][2];
#pragma unroll
        for (int fm = 0; fm < 4; fm++) {
            const uint32_t* p = &As[buf][(wm * 64 + fm * 16 + g) * AS_STRIDE + tg];
            af[fm][0] = p[0];
            af[fm][1] = p[8 * AS_STRIDE];
            af[fm][2] = p[4];
            af[fm][3] = p[8 * AS_STRIDE + 4];
        }
#pragma unroll
        for (int fn = 0; fn < 4; fn++) {
            const uint32_t* p = &Bs[buf][(wn * 32 + fn * 8 + g) * AS_STRIDE + tg];
            bf[fn][0] = p[0];
            bf[fn][1] = p[4];
        }
#pragma unroll
        for (int fm = 0; fm < 4; fm++)
#pragma unroll
            for (int fn = 0; fn < 4; fn++)
                mma_f16(acc[fm][fn], af[fm], bf[fn]);

        if (kt + 1 < 64) {
            sts_B(buf ^ 1);
            asm volatile("cp.async.wait_group 0;");
        }
        __syncthreads();
    }

#pragma unroll
    for (int fm = 0; fm < 4; fm++)
#pragma unroll
        for (int fn = 0; fn < 4; fn++)
#pragma unroll
            for (int hf = 0; hf < 2; hf++) {
                int row = wm * 64 + fm * 16 + g + hf * 8;
                if (row >= m_rows) continue;
                int col = n0 + wn * 32 + fn * 8 + tg * 2;
                int R = mrow0 + row;
                float v0 = acc[fm][fn][hf * 2 + 0];
                float v1 = acc[fm][fn][hf * 2 + 1];
                const float* bp = bias3 + (size_t)c * HID + col;
                int b = g_batch_of_pos[R >> 6];
                float2 o = make_float2(v0 + bp[0], v1 + bp[1]);
                *(float2*)(out + (size_t)(b * TT + (R & 63)) * HID + col) = o;
            }
}

// ---------------- launch ----------------
extern "C" void kernel_launch(void* const* d_in, const int* in_sizes, int n_in,
                              void* d_out, int out_size) {
    const float* actions   = (const float*)d_in[0];
    const float* timesteps = (const float*)d_in[1];
    const float* W1w       = (const float*)d_in[2];
    const float* W1b       = (const float*)d_in[3];
    const float* W2w       = (const float*)d_in[4];
    const float* W2b       = (const float*)d_in[5];
    const float* W3w       = (const float*)d_in[6];
    const float* W3b       = (const float*)d_in[7];
    const int*   cats      = (const int*)d_in[8];
    float* out = (float*)d_out;

    setup_kernel<<<1, 128>>>(cats);
    tau_kernel<<<BB, 512>>>(timesteps);
    stream_kernel<<<1024, 256>>>(W1w, W1b, W2w, W2b);
    gemm2s_kernel<<<BB, 256>>>(actions, cats);
    gemm3_kernel<<<dim3(96, 8), 256>>>(W3w, W3b, out);
}

// round 17
// speedup vs baseline: 1.5161x; 1.0797x over previous
#include <cuda_runtime.h>
#include <cuda_fp16.h>
#include <cstdint>

#define NUM_EMB 32
#define ADIM 32
#define HID 1024
#define BB 128
#define TT 64
#define ROWS_TOTAL (BB*TT)   /* 8192 grouped rows */

// ---------------- scratch (device globals; no allocs allowed) ----------------
__device__ __half g_h   [(ROWS_TOTAL + 128) * HID]; // grouped hidden (fp16), +pad rows (stay 0)
__device__ float  g_tau [BB * HID];                 // grouped tau (fp32)
__device__ float  g_t2  [BB * HID];                 // grouped tau@W2b + b2 (fp32)
__device__ float  g_w12 [NUM_EMB * ADIM * HID];     // fused W1@W2a per category (fp32)
__device__ float  g_v2  [NUM_EMB * HID];            // b1@W2a per category (fp32)
__device__ int    g_batch_of_pos[BB];
__device__ int    g_seg_start[NUM_EMB + 1];
__device__ int    g_mb_cat[128], g_mb_row[128], g_mb_rows[128];
__device__ int    g_mb_count;

// ---------------- helpers ----------------
__device__ __forceinline__ void cpasync16(void* dst, const void* src) {
    unsigned s = (unsigned)__cvta_generic_to_shared(dst);
    asm volatile("cp.async.cg.shared.global [%0], [%1], 16;" :: "r"(s), "l"(src));
}
// fp16 MMA, fp32 accumulate: D(16x8) += A(16x16) * B(16x8)
__device__ __forceinline__ void mma_f16(float c[4], const unsigned a[4], const unsigned b[2]) {
    asm volatile(
        "mma.sync.aligned.m16n8k16.row.col.f32.f16.f16.f32 "
        "{%0,%1,%2,%3}, {%4,%5,%6,%7}, {%8,%9}, {%0,%1,%2,%3};"
        : "+f"(c[0]), "+f"(c[1]), "+f"(c[2]), "+f"(c[3])
        : "r"(a[0]), "r"(a[1]), "r"(a[2]), "r"(a[3]), "r"(b[0]), "r"(b[1]));
}

// ---------------- kernel 0: category grouping + mblock table (parallel) ----------------
__global__ void setup_kernel(const int* __restrict__ cats) {
    __shared__ int cnt[NUM_EMB], segs[NUM_EMB + 1], cur[NUM_EMB];
    int t = threadIdx.x;                 // 128 threads
    if (t < NUM_EMB) cnt[t] = 0;
    __syncthreads();
    int c = cats[t];                     // t in [0, BB)
    atomicAdd(&cnt[c], 1);
    __syncthreads();
    if (t == 0) {
        int s = 0;
        for (int i = 0; i < NUM_EMB; i++) { segs[i] = s; cur[i] = s; s += cnt[i]; }
        segs[NUM_EMB] = s;
    }
    __syncthreads();
    if (t <= NUM_EMB) g_seg_start[t] = segs[t];
    int p = atomicAdd(&cur[c], 1);
    g_batch_of_pos[p] = t;
    __syncthreads();
    if (t == 0) {
        int nmb = 0;
        for (int i = 0; i < NUM_EMB; i++) {
            int rows = cnt[i] * TT;
            int r0 = segs[i] * TT;
            for (int r = 0; r < rows; r += 128) {
                g_mb_cat[nmb] = i;
                g_mb_row[nmb] = r0 + r;
                g_mb_rows[nmb] = (rows - r < 128) ? (rows - r) : 128;
                nmb++;
            }
        }
        g_mb_count = nmb;
    }
}

// ---------------- kernel 1: tau (fp64 trig, grouped layout) ----------------
__global__ void tau_kernel(const float* __restrict__ ts) {
    int pos = blockIdx.x;
    int j = threadIdx.x;               // 0..511
    int b = g_batch_of_pos[pos];
    double t = (double)ts[b];
    double f = exp(-9.210340371976184 * ((double)j) / 512.0);
    double ph = t * f;
    g_tau[pos * HID + j]       = (float)sin(ph);
    g_tau[pos * HID + 512 + j] = (float)cos(ph);
}

// ---------------- kernel 2: fused W2 streamer ----------------
// blocks [0,512):   w12 part — W12[c] = [W1[c]; b1[c]] @ W2a[c], n-tiles of 64 (fp16 MMA)
// blocks [512,1024): t2 part — t2 = tau @ W2b[c] + b2, n-tiles of 64 (SIMT fp32)
#define WS 12   /* 32-bit words per 16-half row */
__global__ __launch_bounds__(256)
void stream_kernel(const float* __restrict__ W1w,
                   const float* __restrict__ W1b,
                   const float* __restrict__ W2w,
                   const float* __restrict__ W2bias) {
    __shared__ float smem_f[10240];      // 40 KB, shared by both parts
    int bid = blockIdx.x;
    int tid = threadIdx.x;

    if (bid < 512) {
        // ================= w12 part =================
        uint32_t* As = (uint32_t*)smem_f;            // 2 x 48 x WS = 1152 words
        uint32_t* Bs = (uint32_t*)smem_f + 1152;     // 2 x 64 x WS = 1536 words
        int c = bid >> 4, n0 = (bid & 15) * 64;
        int lane = tid & 31, wid = tid >> 5;
        int g = lane >> 2, tg = lane & 3;
        int nw0 = wid * 8;                           // warp's 8-column slice
        const float* W1 = W1w + (size_t)c * ADIM * HID;
        const float* b1 = W1b + (size_t)c * HID;
        const float* Bg = W2w + (size_t)c * 2048 * HID;   // rows [0,1024) = W2a

        // zero A pad rows 33..47 (read by MMA as zeros) in both buffers
        for (int i = tid; i < 2 * 15 * WS; i += 256) {
            int bu = i / (15 * WS), r = i % (15 * WS);
            As[bu * 48 * WS + 33 * WS + r] = 0;
        }

        float acc[3][4];
#pragma unroll
        for (int a = 0; a < 3; a++)
#pragma unroll
            for (int i = 0; i < 4; i++) acc[a][i] = 0.f;

        float4 ar;                                   // A regs (tid<132)
        auto ldgA = [&](int kt) {
            if (tid < 132) {
                int a = tid >> 2, q = tid & 3;
                const float* src = (a < 32 ? W1 + (size_t)a * HID : b1) + kt * 16 + q * 4;
                ar = *(const float4*)src;
            }
        };
        auto stsA = [&](int buf) {
            if (tid < 132) {
                int a = tid >> 2, q = tid & 3;
                __half2 h0 = __floats2half2_rn(ar.x, ar.y);
                __half2 h1 = __floats2half2_rn(ar.z, ar.w);
                As[buf * 48 * WS + a * WS + q * 2]     = *(uint32_t*)&h0;
                As[buf * 48 * WS + a * WS + q * 2 + 1] = *(uint32_t*)&h1;
            }
        };
        int nB = tid & 63, kqB = tid >> 6;           // thread owns (n, 4 k-values)
        float br[4];
        auto ldgB = [&](int kt) {
            const float* s = Bg + (size_t)(kt * 16 + kqB * 4) * HID + n0 + nB;
#pragma unroll
            for (int i = 0; i < 4; i++) br[i] = s[(size_t)i * HID];
        };
        auto stsB = [&](int buf) {
            __half2 h0 = __floats2half2_rn(br[0], br[1]);
            __half2 h1 = __floats2half2_rn(br[2], br[3]);
            uint2 v; v.x = *(uint32_t*)&h0; v.y = *(uint32_t*)&h1;
            *(uint2*)&Bs[buf * 64 * WS + nB * WS + kqB * 2] = v;
        };

        ldgB(0); ldgA(0);
        stsB(0); stsA(0);
        __syncthreads();

        for (int kt = 0; kt < 64; kt++) {
            int buf = kt & 1;
            if (kt + 1 < 64) { ldgB(kt + 1); ldgA(kt + 1); }

            unsigned af[3][4], bf[2];
#pragma unroll
            for (int fm = 0; fm < 3; fm++) {
                const uint32_t* p = &As[buf * 48 * WS + (fm * 16 + g) * WS + tg];
                af[fm][0] = p[0];
                af[fm][1] = p[8 * WS];
                af[fm][2] = p[4];
                af[fm][3] = p[8 * WS + 4];
            }
            {
                const uint32_t* p = &Bs[buf * 64 * WS + (nw0 + g) * WS + tg];
                bf[0] = p[0];
                bf[1] = p[4];
            }
#pragma unroll
            for (int fm = 0; fm < 3; fm++)
                mma_f16(acc[fm], af[fm], bf);

            if (kt + 1 < 64) { stsB(buf ^ 1); stsA(buf ^ 1); }
            __syncthreads();
        }

        // epilogue: rows<32 -> g_w12; row 32 -> g_v2
#pragma unroll
        for (int fm = 0; fm < 3; fm++)
#pragma unroll
            for (int hf = 0; hf < 2; hf++) {
                int row = fm * 16 + g + hf * 8;
                int col = n0 + nw0 + tg * 2;
                float v0 = acc[fm][hf * 2 + 0];
                float v1 = acc[fm][hf * 2 + 1];
                if (row < 32) {
                    *(float2*)&g_w12[(size_t)(c * ADIM + row) * HID + col] = make_float2(v0, v1);
                } else if (row == 32) {
                    *(float2*)&g_v2[(size_t)c * HID + col] = make_float2(v0, v1);
                }
            }
    } else {
        // ================= t2 part =================
        float (*tauS)[HID] = (float(*)[HID])smem_f;                  // 8 x 1024
        float (*red)[8][64] = (float(*)[8][64])(smem_f + 8192);      // 4 x 8 x 64
        int idx = bid - 512;
        int c = idx >> 4, nt = idx & 15;
        int lane = tid & 63;
        int kg = tid >> 6;               // 0..3 (k-slices of 256)
        int n = nt * 64 + lane;
        int s0 = g_seg_start[c], s1 = g_seg_start[c + 1];
        const float* Wb = W2w + ((size_t)c * 2048 + 1024) * HID;
        for (int p0 = s0; p0 < s1; p0 += 8) {
            int pc = s1 - p0; if (pc > 8) pc = 8;
            for (int i = tid; i < 8 * HID; i += 256)
                tauS[i >> 10][i & 1023] =
                    (i < pc * HID) ? g_tau[(size_t)(p0 + (i >> 10)) * HID + (i & 1023)] : 0.f;
            __syncthreads();
            float acc[8];
#pragma unroll
            for (int q = 0; q < 8; q++) acc[q] = 0.f;
            int kbeg = kg * 256;
            for (int k = kbeg; k < kbeg + 256; k += 8) {
                float w[8];
#pragma unroll
                for (int i = 0; i < 8; i++) w[i] = Wb[(size_t)(k + i) * HID + n];
#pragma unroll
                for (int i = 0; i < 8; i++)
#pragma unroll
                    for (int q = 0; q < 8; q++) acc[q] += tauS[q][k + i] * w[i];
            }
#pragma unroll
            for (int q = 0; q < 8; q++) red[kg][q][lane] = acc[q];
            __syncthreads();
            if (kg == 0) {
                float bv = W2bias[(size_t)c * HID + n];
                for (int q = 0; q < pc; q++) {
                    float v = red[0][q][lane] + red[1][q][lane] +
                              red[2][q][lane] + red[3][q][lane] + bv;
                    g_t2[(size_t)(p0 + q) * HID + n] = v;
                }
            }
            __syncthreads();
        }
    }
}

// ---------------- kernel 3: hidden = silu(actions @ W12 + v2 + t2) -> g_h fp16 ----------------
// grid (128 pos, 4 n-tiles of 256), 256 threads, ONE column per thread.
// X reads via float4 LDS (4x fewer shared accesses); W12 column in registers.
__global__ __launch_bounds__(256)
void gemm2s_kernel(const float* __restrict__ actions,
                   const int*   __restrict__ cats) {
    __shared__ float Xs[TT * ADIM];
    int pos = blockIdx.x;
    int tid = threadIdx.x;
    int b = g_batch_of_pos[pos];
    int c = cats[b];
    // cooperative X tile load (2048 floats, float4-coalesced)
    {
        const float4* src = (const float4*)(actions + (size_t)b * TT * ADIM);
        float4* dst = (float4*)Xs;
        for (int i = tid; i < TT * ADIM / 4; i += 256) dst[i] = src[i];
    }
    __syncthreads();
    int n = blockIdx.y * 256 + tid;
    const float* W = g_w12 + (size_t)c * ADIM * HID;
    float w[ADIM];
#pragma unroll
    for (int k = 0; k < ADIM; k++) w[k] = W[(size_t)k * HID + n];    // coalesced across tid
    float bn = g_v2[(size_t)c * HID + n] + g_t2[(size_t)pos * HID + n];
    __half* hout = g_h + (size_t)(pos * TT) * HID + n;
    for (int m = 0; m < TT; m++) {
        const float4* xr = (const float4*)(Xs + m * ADIM);
        float acc = bn;
#pragma unroll
        for (int q = 0; q < ADIM / 4; q++) {
            float4 x = xr[q];                                         // LDS.128 broadcast
            acc += x.x * w[q * 4 + 0] + x.y * w[q * 4 + 1]
                 + x.z * w[q * 4 + 2] + x.w * w[q * 4 + 3];
        }
        float v = acc / (1.f + expf(-acc));                           // silu
        hout[(size_t)m * HID] = __float2half_rn(v);
    }
}

// ---------------- kernel 4: out = g_h @ W3 + b3 (fp16 tensor GEMM, scatter) ----------------
#define AS_STRIDE 12
#define TILE_WORDS (128 * AS_STRIDE)

__global__ __launch_bounds__(256, 2)
void gemm3_kernel(const float* __restrict__ Bbase,
                  const float* __restrict__ bias3,
                  float* __restrict__ out) {
    __shared__ uint32_t As[2][TILE_WORDS];
    __shared__ uint32_t Bs[2][TILE_WORDS];

    int mb = blockIdx.x;
    if (mb >= g_mb_count) return;
    const __half* Ag = g_h;
    int c = g_mb_cat[mb], mrow0 = g_mb_row[mb], m_rows = g_mb_rows[mb];
    int n0 = blockIdx.y * 128;
    const float* Bg = Bbase + (size_t)c * HID * HID;

    int tid = threadIdx.x, lane = tid & 31, wid = tid >> 5;
    int wm = wid >> 2, wn = wid & 3;    // 2 x 4 warp grid, warp tile 64x32
    int g = lane >> 2, tg = lane & 3;

    float acc[4][4][4];
#pragma unroll
    for (int a = 0; a < 4; a++)
#pragma unroll
        for (int b = 0; b < 4; b++)
#pragma unroll
            for (int i = 0; i < 4; i++) acc[a][b][i] = 0.f;

    int rowA = tid >> 1, hsA = tid & 1;
    auto load_A = [&](int kt, int buf) {
        cpasync16(&As[buf][rowA * AS_STRIDE + hsA * 4],
                  Ag + (size_t)(mrow0 + rowA) * HID + kt * 16 + hsA * 8);
    };
    int nB = tid & 127, khB = tid >> 7;
    float br[8];
    auto ldg_B = [&](int kt) {
        const float* s = Bg + (size_t)(kt * 16 + khB * 8) * HID + n0 + nB;
#pragma unroll
        for (int i = 0; i < 8; i++) br[i] = s[(size_t)i * HID];
    };
    auto sts_B = [&](int buf) {
        uint4 v;
        __half2 h0 = __floats2half2_rn(br[0], br[1]);
        __half2 h1 = __floats2half2_rn(br[2], br[3]);
        __half2 h2 = __floats2half2_rn(br[4], br[5]);
        __half2 h3 = __floats2half2_rn(br[6], br[7]);
        v.x = *(uint32_t*)&h0; v.y = *(uint32_t*)&h1;
        v.z = *(uint32_t*)&h2; v.w = *(uint32_t*)&h3;
        *(uint4*)&Bs[buf][nB * AS_STRIDE + khB * 4] = v;
    };

    ldg_B(0);
    load_A(0, 0);
    asm volatile("cp.async.commit_group;");
    sts_B(0);
    asm volatile("cp.async.wait_group 0;");
    __syncthreads();

    for (int kt = 0; kt < 64; kt++) {
        int buf = kt & 1;
        if (kt + 1 < 64) {
            ldg_B(kt + 1);
            load_A(kt + 1, buf ^ 1);
            asm volatile("cp.async.commit_group;");
        }
        unsigned af[4][4], bf[4][2];
#pragma unroll
        for (int fm = 0; fm < 4; fm++) {
            const uint32_t* p = &As[buf][(wm * 64 + fm * 16 + g) * AS_STRIDE + tg];
            af[fm][0] = p[0];
            af[fm][1] = p[8 * AS_STRIDE];
            af[fm][2] = p[4];
            af[fm][3] = p[8 * AS_STRIDE + 4];
        }
#pragma unroll
        for (int fn = 0; fn < 4; fn++) {
            const uint32_t* p = &Bs[buf][(wn * 32 + fn * 8 + g) * AS_STRIDE + tg];
            bf[fn][0] = p[0];
            bf[fn][1] = p[4];
        }
#pragma unroll
        for (int fm = 0; fm < 4; fm++)
#pragma unroll
            for (int fn = 0; fn < 4; fn++)
                mma_f16(acc[fm][fn], af[fm], bf[fn]);

        if (kt + 1 < 64) {
            sts_B(buf ^ 1);
            asm volatile("cp.async.wait_group 0;");
        }
        __syncthreads();
    }

#pragma unroll
    for (int fm = 0; fm < 4; fm++)
#pragma unroll
        for (int fn = 0; fn < 4; fn++)
#pragma unroll
            for (int hf = 0; hf < 2; hf++) {
                int row = wm * 64 + fm * 16 + g + hf * 8;
                if (row >= m_rows) continue;
                int col = n0 + wn * 32 + fn * 8 + tg * 2;
                int R = mrow0 + row;
                float v0 = acc[fm][fn][hf * 2 + 0];
                float v1 = acc[fm][fn][hf * 2 + 1];
                const float* bp = bias3 + (size_t)c * HID + col;
                int b = g_batch_of_pos[R >> 6];
                float2 o = make_float2(v0 + bp[0], v1 + bp[1]);
                *(float2*)(out + (size_t)(b * TT + (R & 63)) * HID + col) = o;
            }
}

// ---------------- launch ----------------
extern "C" void kernel_launch(void* const* d_in, const int* in_sizes, int n_in,
                              void* d_out, int out_size) {
    const float* actions   = (const float*)d_in[0];
    const float* timesteps = (const float*)d_in[1];
    const float* W1w       = (const float*)d_in[2];
    const float* W1b       = (const float*)d_in[3];
    const float* W2w       = (const float*)d_in[4];
    const float* W2b       = (const float*)d_in[5];
    const float* W3w       = (const float*)d_in[6];
    const float* W3b       = (const float*)d_in[7];
    const int*   cats      = (const int*)d_in[8];
    float* out = (float*)d_out;

    setup_kernel<<<1, 128>>>(cats);
    tau_kernel<<<BB, 512>>>(timesteps);
    stream_kernel<<<1024, 256>>>(W1w, W1b, W2w, W2b);
    gemm2s_kernel<<<dim3(BB, 4), 256>>>(actions, cats);
    gemm3_kernel<<<dim3(96, 8), 256>>>(W3w, W3b, out);
}